// round 3
// baseline (speedup 1.0000x reference)
#include <cuda_runtime.h>
#include <math_constants.h>

// Problem constants (from reference setup_inputs)
#define BATCH   8
#define NPTS    4096
#define NDIM    3

#define THREADS 128
#define PTS     8                    // x points per thread (4 packed f32x2 pairs)
#define XCHUNK  (THREADS * PTS)      // 1024
#define NXCH    (NPTS / XCHUNK)      // 4
#define YCHUNK  512                  // y points per block tile
#define NYCH    (NPTS / YCHUNK)      // 8
#define NWARPS  (THREADS / 32)       // 4

// Min of s = (|p|^2 + |q|^2)/2 - p.q  (= d^2/2), as monotone uint keys.
// [0 .. B*N):      row mins  (x -> y direction)
// [B*N .. 2*B*N):  col mins  (y -> x direction)
__device__ unsigned int g_minkey[2 * BATCH * NPTS];

__device__ __forceinline__ unsigned long long ffma2(unsigned long long a,
                                                    unsigned long long b,
                                                    unsigned long long c) {
    unsigned long long d;
    asm("fma.rn.f32x2 %0, %1, %2, %3;" : "=l"(d) : "l"(a), "l"(b), "l"(c));
    return d;
}

__device__ __forceinline__ unsigned long long fadd2(unsigned long long a,
                                                    unsigned long long b) {
    unsigned long long d;
    asm("add.rn.f32x2 %0, %1, %2;" : "=l"(d) : "l"(a), "l"(b));
    return d;
}

__device__ __forceinline__ unsigned long long pack2(float lo, float hi) {
    unsigned long long r;
    asm("mov.b64 %0, {%1, %2};" : "=l"(r) : "f"(lo), "f"(hi));
    return r;
}

__device__ __forceinline__ unsigned int fkey(float f) {
    unsigned int u = __float_as_uint(f);
    return u ^ (((unsigned int)((int)u >> 31)) | 0x80000000u);
}

__global__ void chamfer_init_kernel() {
    int i = blockIdx.x * blockDim.x + threadIdx.x;
    if (i < 2 * BATCH * NPTS) g_minkey[i] = 0xFF800000u;  // fkey(+inf)
}

__global__ __launch_bounds__(THREADS)
void chamfer_pairs_kernel(const float* __restrict__ x,
                          const float* __restrict__ y) {
    const int b = blockIdx.z;

    // Shared q tile: per point {qx,qx},{qy,qy},{qz,qz},{hq,hq}, hq = |q|^2/2.
    __shared__ unsigned long long sq[YCHUNK * 4];
    __shared__ float colbuf[NWARPS][YCHUNK];

    const int tid  = threadIdx.x;
    const int warp = tid >> 5;
    const int lane = tid & 31;

    const float* __restrict__ Qb =
        y + ((size_t)b * NPTS + (size_t)blockIdx.y * YCHUNK) * NDIM;
    for (int j = tid; j < YCHUNK; j += THREADS) {
        float qx = Qb[j * 3 + 0];
        float qy = Qb[j * 3 + 1];
        float qz = Qb[j * 3 + 2];
        float hq = 0.5f * fmaf(qz, qz, fmaf(qy, qy, qx * qx));
        sq[j * 4 + 0] = pack2(qx, qx);
        sq[j * 4 + 1] = pack2(qy, qy);
        sq[j * 4 + 2] = pack2(qz, qz);
        sq[j * 4 + 3] = pack2(hq, hq);
    }
    __syncthreads();

    // Register setup: 8 x-points as 4 packed pairs of negated comps + hp.
    const int pbase = blockIdx.x * XCHUNK + tid;
    const float* __restrict__ Pb = x + (size_t)b * NPTS * NDIM;

    float px[PTS], py[PTS], pz[PTS], hpv[PTS];
#pragma unroll
    for (int p = 0; p < PTS; p++) {
        int idx = pbase + p * THREADS;
        px[p] = Pb[idx * 3 + 0];
        py[p] = Pb[idx * 3 + 1];
        pz[p] = Pb[idx * 3 + 2];
        hpv[p] = 0.5f * fmaf(pz[p], pz[p], fmaf(py[p], py[p], px[p] * px[p]));
    }
    unsigned long long npx[4], npy[4], npz[4], hp2[4];
#pragma unroll
    for (int pp = 0; pp < 4; pp++) {
        npx[pp] = pack2(-px[2 * pp], -px[2 * pp + 1]);
        npy[pp] = pack2(-py[2 * pp], -py[2 * pp + 1]);
        npz[pp] = pack2(-pz[2 * pp], -pz[2 * pp + 1]);
        hp2[pp] = pack2(hpv[2 * pp], hpv[2 * pp + 1]);
    }

    float rmn[PTS];
#pragma unroll
    for (int p = 0; p < PTS; p++) rmn[p] = CUDART_INF_F;

    const ulonglong2* __restrict__ sp = (const ulonglong2*)sq;

    // Main loop: each j yields 8 unique pair values s = d^2/2, feeding both
    // the register row-mins and the warp-reduced col-min.
#pragma unroll 2
    for (int j = 0; j < YCHUNK; j++) {
        ulonglong2 A  = sp[2 * j + 0];   // .x={qx,qx} .y={qy,qy}
        ulonglong2 Bv = sp[2 * j + 1];   // .x={qz,qz} .y={hq,hq}

        float cpre[4];
#pragma unroll
        for (int pp = 0; pp < 4; pp++) {
            unsigned long long acc = ffma2(npx[pp], A.x, hp2[pp]);
            acc = ffma2(npy[pp], A.y, acc);
            acc = ffma2(npz[pp], Bv.x, acc);
            unsigned long long s = fadd2(acc, Bv.y);
            float slo = __uint_as_float((unsigned int)s);
            float shi = __uint_as_float((unsigned int)(s >> 32));
            rmn[2 * pp]     = fminf(rmn[2 * pp], slo);
            rmn[2 * pp + 1] = fminf(rmn[2 * pp + 1], shi);
            cpre[pp] = fminf(slo, shi);
        }
        float cc = fminf(fminf(cpre[0], cpre[1]), fminf(cpre[2], cpre[3]));
        cc = fminf(cc, __shfl_xor_sync(0xFFFFFFFFu, cc, 16));
        cc = fminf(cc, __shfl_xor_sync(0xFFFFFFFFu, cc, 8));
        cc = fminf(cc, __shfl_xor_sync(0xFFFFFFFFu, cc, 4));
        cc = fminf(cc, __shfl_xor_sync(0xFFFFFFFFu, cc, 2));
        cc = fminf(cc, __shfl_xor_sync(0xFFFFFFFFu, cc, 1));
        if (lane == 0) colbuf[warp][j] = cc;
    }

    // Row partial mins -> global (REDG: result unused).
    unsigned int* grow = g_minkey + (size_t)b * NPTS;
#pragma unroll
    for (int p = 0; p < PTS; p++) {
        atomicMin(&grow[pbase + p * THREADS], fkey(rmn[p]));
    }

    __syncthreads();

    // Col mins: merge the 4 warp strips, then one REDG per column.
    unsigned int* gcol = g_minkey + (size_t)BATCH * NPTS + (size_t)b * NPTS
                       + (size_t)blockIdx.y * YCHUNK;
    for (int j = tid; j < YCHUNK; j += THREADS) {
        float m = fminf(fminf(colbuf[0][j], colbuf[1][j]),
                        fminf(colbuf[2][j], colbuf[3][j]));
        atomicMin(&gcol[j], fkey(m));
    }
}

__global__ __launch_bounds__(1024)
void chamfer_reduce_kernel(float* __restrict__ out) {
    __shared__ float ssum[1024];
    float s = 0.0f;
    for (int i = threadIdx.x; i < 2 * BATCH * NPTS; i += 1024) {
        unsigned int k = g_minkey[i];
        unsigned int u = (k & 0x80000000u) ? (k ^ 0x80000000u) : ~k;
        float halfd2 = __uint_as_float(u);
        s += sqrtf(fmaxf(2.0f * halfd2, 0.0f));
    }
    ssum[threadIdx.x] = s;
    __syncthreads();
    for (int off = 512; off > 0; off >>= 1) {
        if (threadIdx.x < off) ssum[threadIdx.x] += ssum[threadIdx.x + off];
        __syncthreads();
    }
    if (threadIdx.x == 0) out[0] = ssum[0] / (float)(BATCH * NPTS);
}

extern "C" void kernel_launch(void* const* d_in, const int* in_sizes, int n_in,
                              void* d_out, int out_size) {
    const float* x = (const float*)d_in[0];
    const float* y = (const float*)d_in[1];
    float* out = (float*)d_out;

    chamfer_init_kernel<<<(2 * BATCH * NPTS + 255) / 256, 256>>>();

    dim3 grid(NXCH, NYCH, BATCH);   // 4 x 8 x 8 = 256 blocks, one matrix pass
    chamfer_pairs_kernel<<<grid, THREADS>>>(x, y);

    chamfer_reduce_kernel<<<1, 1024>>>(out);
}

// round 5
// speedup vs baseline: 1.5711x; 1.5711x over previous
#include <cuda_runtime.h>
#include <math_constants.h>

// Problem constants (from reference setup_inputs)
#define BATCH   8
#define NPTS    4096
#define NDIM    3

#define THREADS 128
#define PTS     4                    // x points per thread
#define XCHUNK  (THREADS * PTS)      // 512
#define NXCH    (NPTS / XCHUNK)      // 8
#define YCHUNK  64                   // y points per block tile
#define NYCH    (NPTS / YCHUNK)      // 64

// Min of s = (|p|^2 + |q|^2)/2 - p.q  (= d^2/2), stored as INVERTED monotone
// keys so the atomicMax identity is 0 (static zero-init; no init kernel).
// [0 .. B*N):      row mins  (x -> y)
// [B*N .. 2*B*N):  col mins  (y -> x)
__device__ unsigned int g_minkey[2 * BATCH * NPTS];   // zero-initialized

// Inverted monotone key: f1 < f2  <=>  key(f1) > key(f2); key(finite) > 0.
__device__ __forceinline__ unsigned int fkeyenc(float f) {
    unsigned int u = __float_as_uint(f);
    unsigned int m = ((unsigned int)((int)u >> 31)) | 0x80000000u;
    return ~(u ^ m);
}

__device__ __forceinline__ float fkeydec(unsigned int k) {
    unsigned int fk = ~k;
    unsigned int u = (fk & 0x80000000u) ? (fk ^ 0x80000000u) : ~fk;
    return __uint_as_float(u);
}

__global__ __launch_bounds__(THREADS)
void chamfer_pairs_kernel(const float* __restrict__ x,
                          const float* __restrict__ y) {
    const int b = blockIdx.z;

    // q tile: (qx, qy, qz, hq) with hq = |q|^2/2 — one LDS.128 per j.
    __shared__ float4 sq[YCHUNK];
    // Per-thread column partials; row-major so the hot-loop STS is
    // conflict-free (consecutive tids -> consecutive banks). +1 pad for the
    // epilogue read pattern.
    __shared__ float colpartial[YCHUNK][THREADS + 1];

    const int tid = threadIdx.x;

    const float* __restrict__ Qb =
        y + ((size_t)b * NPTS + (size_t)blockIdx.y * YCHUNK) * NDIM;
    if (tid < YCHUNK) {
        float qx = Qb[tid * 3 + 0];
        float qy = Qb[tid * 3 + 1];
        float qz = Qb[tid * 3 + 2];
        float hq = 0.5f * fmaf(qz, qz, fmaf(qy, qy, qx * qx));
        sq[tid] = make_float4(qx, qy, qz, hq);
    }
    __syncthreads();

    const int pbase = blockIdx.x * XCHUNK + tid;
    const float* __restrict__ Pb = x + (size_t)b * NPTS * NDIM;

    float px[PTS], py[PTS], pz[PTS], hp[PTS], rmn[PTS];
#pragma unroll
    for (int p = 0; p < PTS; p++) {
        int idx = pbase + p * THREADS;
        px[p] = Pb[idx * 3 + 0];
        py[p] = Pb[idx * 3 + 1];
        pz[p] = Pb[idx * 3 + 2];
        hp[p] = 0.5f * fmaf(pz[p], pz[p], fmaf(py[p], py[p], px[p] * px[p]));
        rmn[p] = CUDART_INF_F;
    }

    // Hot loop: per j, 4 unique pairs.
    //   s_p = hq - p.q        (3 FFMA; rows add hp after the min)
    //   col partial = min_p (s_p + hp_p)   (4 FADD + 3 FMNMX + 1 STS)
#pragma unroll 8
    for (int j = 0; j < YCHUNK; j++) {
        float4 q = sq[j];
        float s[PTS];
#pragma unroll
        for (int p = 0; p < PTS; p++) {
            float t = fmaf(-px[p], q.x, q.w);
            t = fmaf(-py[p], q.y, t);
            t = fmaf(-pz[p], q.z, t);
            s[p] = t;
            rmn[p] = fminf(rmn[p], t);
        }
        float c01 = fminf(s[0] + hp[0], s[1] + hp[1]);
        float c23 = fminf(s[2] + hp[2], s[3] + hp[3]);
        colpartial[j][tid] = fminf(c01, c23);
    }

    // Row partial mins -> global (inverted keys, atomicMax, result unused).
    unsigned int* grow = g_minkey + (size_t)b * NPTS;
#pragma unroll
    for (int p = 0; p < PTS; p++) {
        atomicMax(&grow[pbase + p * THREADS], fkeyenc(rmn[p] + hp[p]));
    }

    __syncthreads();

    // Column epilogue: thread pair (2j, 2j+1) reduces column j's 128 partials.
    {
        const int j = tid >> 1;
        const int half = tid & 1;
        const float* cp = &colpartial[j][half * (THREADS / 2)];
        float m = CUDART_INF_F;
#pragma unroll 8
        for (int i = 0; i < THREADS / 2; i++) m = fminf(m, cp[i]);
        m = fminf(m, __shfl_xor_sync(0xFFFFFFFFu, m, 1));
        if (half == 0) {
            unsigned int* gcol = g_minkey + (size_t)BATCH * NPTS
                               + (size_t)b * NPTS + (size_t)blockIdx.y * YCHUNK;
            atomicMax(&gcol[j], fkeyenc(m));
        }
    }
}

__global__ __launch_bounds__(1024)
void chamfer_reduce_kernel(float* __restrict__ out) {
    __shared__ float ssum[1024];
    float s = 0.0f;
    for (int i = threadIdx.x; i < 2 * BATCH * NPTS; i += 1024) {
        float halfd2 = fkeydec(g_minkey[i]);
        s += sqrtf(fmaxf(2.0f * halfd2, 0.0f));
        g_minkey[i] = 0u;   // reset for the next graph replay
    }
    ssum[threadIdx.x] = s;
    __syncthreads();
    for (int off = 512; off > 0; off >>= 1) {
        if (threadIdx.x < off) ssum[threadIdx.x] += ssum[threadIdx.x + off];
        __syncthreads();
    }
    if (threadIdx.x == 0) out[0] = ssum[0] / (float)(BATCH * NPTS);
}

extern "C" void kernel_launch(void* const* d_in, const int* in_sizes, int n_in,
                              void* d_out, int out_size) {
    const float* x = (const float*)d_in[0];
    const float* y = (const float*)d_in[1];
    float* out = (float*)d_out;

    dim3 grid(NXCH, NYCH, BATCH);   // 8 x 64 x 8 = 4096 blocks
    chamfer_pairs_kernel<<<grid, THREADS>>>(x, y);

    chamfer_reduce_kernel<<<1, 1024>>>(out);
}

// round 6
// speedup vs baseline: 2.2290x; 1.4188x over previous
#include <cuda_runtime.h>
#include <math_constants.h>

// Problem constants (from reference setup_inputs)
#define BATCH   8
#define NPTS    4096
#define NDIM    3

#define THREADS 128
#define PTS     4                    // x points per thread
#define XCHUNK  (THREADS * PTS)      // 512
#define NXCH    (NPTS / XCHUNK)      // 8
#define YCHUNK  64                   // y points per block tile
#define NYCH    (NPTS / YCHUNK)      // 64

#define NKEYS   (2 * BATCH * NPTS)   // 65536
#define RBLK    128                  // partial-reduce blocks
#define RTHR    256                  // partial-reduce threads/block
#define RPT     (NKEYS / (RBLK * RTHR))  // 2 keys per thread

// Min of s = (|p|^2 + |q|^2)/2 - p.q  (= d^2/2), stored as INVERTED monotone
// keys so the atomicMax identity is 0 (static zero-init; no init kernel).
// [0 .. B*N):      row mins  (x -> y)
// [B*N .. 2*B*N):  col mins  (y -> x)
__device__ unsigned int g_minkey[NKEYS];   // zero-initialized
__device__ float g_partial[RBLK];          // pure overwrite each replay

// Inverted monotone key: f1 < f2  <=>  key(f1) > key(f2); key(finite) > 0.
__device__ __forceinline__ unsigned int fkeyenc(float f) {
    unsigned int u = __float_as_uint(f);
    unsigned int m = ((unsigned int)((int)u >> 31)) | 0x80000000u;
    return ~(u ^ m);
}

__device__ __forceinline__ float fkeydec(unsigned int k) {
    unsigned int fk = ~k;
    unsigned int u = (fk & 0x80000000u) ? (fk ^ 0x80000000u) : ~fk;
    return __uint_as_float(u);
}

__global__ __launch_bounds__(THREADS)
void chamfer_pairs_kernel(const float* __restrict__ x,
                          const float* __restrict__ y) {
    const int b = blockIdx.z;

    // q tile: (qx, qy, qz, hq) with hq = |q|^2/2 — one LDS.128 per j.
    __shared__ float4 sq[YCHUNK];
    // Per-thread column partials; row-major so the hot-loop STS is
    // conflict-free (consecutive tids -> consecutive banks).
    __shared__ float colpartial[YCHUNK][THREADS + 1];

    const int tid = threadIdx.x;

    const float* __restrict__ Qb =
        y + ((size_t)b * NPTS + (size_t)blockIdx.y * YCHUNK) * NDIM;
    if (tid < YCHUNK) {
        float qx = Qb[tid * 3 + 0];
        float qy = Qb[tid * 3 + 1];
        float qz = Qb[tid * 3 + 2];
        float hq = 0.5f * fmaf(qz, qz, fmaf(qy, qy, qx * qx));
        sq[tid] = make_float4(qx, qy, qz, hq);
    }
    __syncthreads();

    const int pbase = blockIdx.x * XCHUNK + tid;
    const float* __restrict__ Pb = x + (size_t)b * NPTS * NDIM;

    float px[PTS], py[PTS], pz[PTS], hp[PTS], rmn[PTS];
#pragma unroll
    for (int p = 0; p < PTS; p++) {
        int idx = pbase + p * THREADS;
        px[p] = Pb[idx * 3 + 0];
        py[p] = Pb[idx * 3 + 1];
        pz[p] = Pb[idx * 3 + 2];
        hp[p] = 0.5f * fmaf(pz[p], pz[p], fmaf(py[p], py[p], px[p] * px[p]));
        rmn[p] = CUDART_INF_F;
    }

    // Hot loop: per j, 4 unique pairs.
    //   s_p = hq - p.q        (3 FFMA; rows add hp after the min)
    //   col partial = min_p (s_p + hp_p)   (4 FADD + 3 FMNMX + 1 STS)
#pragma unroll 8
    for (int j = 0; j < YCHUNK; j++) {
        float4 q = sq[j];
        float s[PTS];
#pragma unroll
        for (int p = 0; p < PTS; p++) {
            float t = fmaf(-px[p], q.x, q.w);
            t = fmaf(-py[p], q.y, t);
            t = fmaf(-pz[p], q.z, t);
            s[p] = t;
            rmn[p] = fminf(rmn[p], t);
        }
        float c01 = fminf(s[0] + hp[0], s[1] + hp[1]);
        float c23 = fminf(s[2] + hp[2], s[3] + hp[3]);
        colpartial[j][tid] = fminf(c01, c23);
    }

    // Row partial mins -> global (inverted keys, atomicMax, result unused).
    unsigned int* grow = g_minkey + (size_t)b * NPTS;
#pragma unroll
    for (int p = 0; p < PTS; p++) {
        atomicMax(&grow[pbase + p * THREADS], fkeyenc(rmn[p] + hp[p]));
    }

    __syncthreads();

    // Column epilogue: thread pair (2j, 2j+1) reduces column j's 128 partials.
    {
        const int j = tid >> 1;
        const int half = tid & 1;
        const float* cp = &colpartial[j][half * (THREADS / 2)];
        float m = CUDART_INF_F;
#pragma unroll 8
        for (int i = 0; i < THREADS / 2; i++) m = fminf(m, cp[i]);
        m = fminf(m, __shfl_xor_sync(0xFFFFFFFFu, m, 1));
        if (half == 0) {
            unsigned int* gcol = g_minkey + (size_t)BATCH * NPTS
                               + (size_t)b * NPTS + (size_t)blockIdx.y * YCHUNK;
            atomicMax(&gcol[j], fkeyenc(m));
        }
    }
}

// Stage 1: 128 blocks each sum a 512-key slice (sqrt of decoded d^2/2) and
// reset their slice of g_minkey for the next graph replay.
__global__ __launch_bounds__(RTHR)
void chamfer_partial_kernel() {
    __shared__ float ssum[RTHR];
    const int base = blockIdx.x * RTHR * RPT + threadIdx.x;
    float s = 0.0f;
#pragma unroll
    for (int r = 0; r < RPT; r++) {
        int i = base + r * RTHR;
        float halfd2 = fkeydec(g_minkey[i]);
        s += sqrtf(fmaxf(2.0f * halfd2, 0.0f));
        g_minkey[i] = 0u;   // exactly-once reset, race-free
    }
    ssum[threadIdx.x] = s;
    __syncthreads();
    for (int off = RTHR / 2; off >= 32; off >>= 1) {
        if (threadIdx.x < off) ssum[threadIdx.x] += ssum[threadIdx.x + off];
        __syncthreads();
    }
    if (threadIdx.x < 32) {
        float v = ssum[threadIdx.x];
        v += __shfl_xor_sync(0xFFFFFFFFu, v, 16);
        v += __shfl_xor_sync(0xFFFFFFFFu, v, 8);
        v += __shfl_xor_sync(0xFFFFFFFFu, v, 4);
        v += __shfl_xor_sync(0xFFFFFFFFu, v, 2);
        v += __shfl_xor_sync(0xFFFFFFFFu, v, 1);
        if (threadIdx.x == 0) g_partial[blockIdx.x] = v;
    }
}

// Stage 2: one warp folds the 128 block partials into the scalar output.
__global__ __launch_bounds__(32)
void chamfer_final_kernel(float* __restrict__ out) {
    float s = 0.0f;
#pragma unroll
    for (int r = 0; r < RBLK / 32; r++) s += g_partial[threadIdx.x + 32 * r];
    s += __shfl_xor_sync(0xFFFFFFFFu, s, 16);
    s += __shfl_xor_sync(0xFFFFFFFFu, s, 8);
    s += __shfl_xor_sync(0xFFFFFFFFu, s, 4);
    s += __shfl_xor_sync(0xFFFFFFFFu, s, 2);
    s += __shfl_xor_sync(0xFFFFFFFFu, s, 1);
    if (threadIdx.x == 0) out[0] = s / (float)(BATCH * NPTS);
}

extern "C" void kernel_launch(void* const* d_in, const int* in_sizes, int n_in,
                              void* d_out, int out_size) {
    const float* x = (const float*)d_in[0];
    const float* y = (const float*)d_in[1];
    float* out = (float*)d_out;

    dim3 grid(NXCH, NYCH, BATCH);   // 8 x 64 x 8 = 4096 blocks
    chamfer_pairs_kernel<<<grid, THREADS>>>(x, y);

    chamfer_partial_kernel<<<RBLK, RTHR>>>();
    chamfer_final_kernel<<<1, 32>>>(out);
}